// round 1
// baseline (speedup 1.0000x reference)
#include <cuda_runtime.h>
#include <cstddef>

#define B_   4096
#define T_   50
#define IN_  4
#define H_   256
#define G4_  1024
#define K_   3
#define FS_  6
#define ROWS 32
#define ST   36            // padded smem row stride (floats): stride-36 keeps 16B align, ~4-way conflicts max
#define NTHREADS 1024
#define NCTA (B_ / ROWS)   // 128

// ---------------- device scratch (no allocs allowed) ----------------
// Interleaved-transposed weights: WT[j][hu*4 + gate] so one float4 load gives
// all 4 gate weights of one hidden unit, coalesced across lanes (consecutive hu).
__device__ float g_WT_ih0[IN_ * G4_];
__device__ float g_WT_hh0[H_ * G4_];
__device__ float g_WT_cat1[2 * H_ * G4_];      // [Wih1^T ; Whh1^T]
__device__ float g_B0[G4_];
__device__ float g_B1[G4_];
__device__ float g_dWT_ih0[K_][2 * G4_];
__device__ float g_dWT_hh0[K_][H_ * G4_];
__device__ float g_dWT_cat1[K_][2 * H_ * G4_];
__device__ float g_dB0[K_][G4_];
__device__ float g_dB1[K_][G4_];
// encoder-final state checkpoint, layout [hu*B_ + b]
__device__ float g_h0e[H_ * B_];
__device__ float g_h1e[H_ * B_];
__device__ float g_c0e[H_ * B_];
__device__ float g_c1e[H_ * B_];

// ---------------- packed fp32x2 helpers (Blackwell FFMA2) ----------------
__device__ __forceinline__ void fma2(unsigned long long& acc,
                                     unsigned long long a,
                                     unsigned long long b) {
    asm("fma.rn.f32x2 %0, %1, %2, %0;" : "+l"(acc) : "l"(a), "l"(b));
}
__device__ __forceinline__ unsigned long long pack2(float x, float y) {
    unsigned long long u;
    asm("mov.b64 %0, {%1, %2};" : "=l"(u) : "f"(x), "f"(y));
    return u;
}
__device__ __forceinline__ float2 unpack2(unsigned long long u) {
    float2 v;
    asm("mov.b64 {%0, %1}, %2;" : "=f"(v.x), "=f"(v.y) : "l"(u));
    return v;
}
__device__ __forceinline__ float sigf(float x)  { return 1.f / (1.f + __expf(-x)); }
__device__ __forceinline__ float tanhx(float x) { return 2.f / (1.f + __expf(-2.f * x)) - 1.f; }

// ---------------- prep: transpose + gate-interleave all weights ----------------
__global__ void prep_kernel(
    const float* __restrict__ eWih0, const float* __restrict__ eWhh0,
    const float* __restrict__ ebih0, const float* __restrict__ ebhh0,
    const float* __restrict__ eWih1, const float* __restrict__ eWhh1,
    const float* __restrict__ ebih1, const float* __restrict__ ebhh1,
    const float* __restrict__ dWih0, const float* __restrict__ dWhh0,
    const float* __restrict__ dbih0, const float* __restrict__ dbhh0,
    const float* __restrict__ dWih1, const float* __restrict__ dWhh1,
    const float* __restrict__ dbih1, const float* __restrict__ dbhh1)
{
    const int N0 = IN_ * G4_;
    const int N1 = H_ * G4_;
    const int N2 = 2 * H_ * G4_;
    const int N3 = G4_, N4 = G4_;
    const int N5 = K_ * 2 * G4_;
    const int N6 = K_ * H_ * G4_;
    const int N7 = K_ * 2 * H_ * G4_;
    const int N8 = K_ * G4_, N9 = K_ * G4_;
    const int TOT = N0 + N1 + N2 + N3 + N4 + N5 + N6 + N7 + N8 + N9;
    for (int idx = blockIdx.x * blockDim.x + threadIdx.x; idx < TOT;
         idx += gridDim.x * blockDim.x) {
        int i = idx;
        if (i < N0) { int j = i / G4_; int u4 = i - j * G4_; int hu = u4 >> 2, g = u4 & 3;
            g_WT_ih0[i] = eWih0[(g * H_ + hu) * IN_ + j]; continue; }
        i -= N0;
        if (i < N1) { int j = i / G4_; int u4 = i - j * G4_; int hu = u4 >> 2, g = u4 & 3;
            g_WT_hh0[i] = eWhh0[(g * H_ + hu) * H_ + j]; continue; }
        i -= N1;
        if (i < N2) { int j = i / G4_; int u4 = i - j * G4_; int hu = u4 >> 2, g = u4 & 3;
            g_WT_cat1[i] = (j < H_) ? eWih1[(g * H_ + hu) * H_ + j]
                                    : eWhh1[(g * H_ + hu) * H_ + (j - H_)]; continue; }
        i -= N2;
        if (i < N3) { int hu = i >> 2, g = i & 3;
            g_B0[i] = ebih0[g * H_ + hu] + ebhh0[g * H_ + hu]; continue; }
        i -= N3;
        if (i < N4) { int hu = i >> 2, g = i & 3;
            g_B1[i] = ebih1[g * H_ + hu] + ebhh1[g * H_ + hu]; continue; }
        i -= N4;
        if (i < N5) { int k = i / (2 * G4_); int rem = i - k * 2 * G4_;
            int j = rem / G4_; int u4 = rem - j * G4_; int hu = u4 >> 2, g = u4 & 3;
            g_dWT_ih0[k][rem] = dWih0[(k * G4_ + g * H_ + hu) * 2 + j]; continue; }
        i -= N5;
        if (i < N6) { int k = i / (H_ * G4_); int rem = i - k * H_ * G4_;
            int j = rem / G4_; int u4 = rem - j * G4_; int hu = u4 >> 2, g = u4 & 3;
            g_dWT_hh0[k][rem] = dWhh0[(k * G4_ + g * H_ + hu) * H_ + j]; continue; }
        i -= N6;
        if (i < N7) { int k = i / (2 * H_ * G4_); int rem = i - k * 2 * H_ * G4_;
            int j = rem / G4_; int u4 = rem - j * G4_; int hu = u4 >> 2, g = u4 & 3;
            g_dWT_cat1[k][rem] = (j < H_) ? dWih1[(k * G4_ + g * H_ + hu) * H_ + j]
                                          : dWhh1[(k * G4_ + g * H_ + hu) * H_ + (j - H_)]; continue; }
        i -= N7;
        if (i < N8) { int k = i / G4_; int rem = i - k * G4_; int hu = rem >> 2, g = rem & 3;
            g_dB0[k][rem] = dbih0[k * G4_ + g * H_ + hu] + dbhh0[k * G4_ + g * H_ + hu]; continue; }
        i -= N8;
        { int k = i / G4_; int rem = i - k * G4_; int hu = rem >> 2, g = rem & 3;
            g_dB1[k][rem] = dbih1[k * G4_ + g * H_ + hu] + dbhh1[k * G4_ + g * H_ + hu]; }
    }
}

// ---------------- hot-loop macros (operate on kernel locals) ----------------
// acc[p][g] : f32x2 accumulator for row pair (r0+2p, r0+2p+1), gate g (i,f,g,o)
#define ACC_INIT(BIAS) {                                                        \
    _Pragma("unroll")                                                           \
    for (int g_ = 0; g_ < 4; ++g_) {                                            \
        float bv_ = (BIAS)[u4 + g_];                                            \
        unsigned long long bp_ = pack2(bv_, bv_);                               \
        acc[0][g_] = bp_; acc[1][g_] = bp_; acc[2][g_] = bp_; acc[3][g_] = bp_; \
    } }

#define GATE_SEG(SRC, NJ, WT) {                                                 \
    const float* __restrict__ wt_ = (WT);                                       \
    const float* __restrict__ sr_ = (SRC);                                      \
    _Pragma("unroll 2")                                                         \
    for (int j = 0; j < (NJ); ++j) {                                            \
        const unsigned long long* hp_ =                                         \
            (const unsigned long long*)(sr_ + j * ST + r0);                     \
        unsigned long long h01 = hp_[0], h23 = hp_[1];                          \
        unsigned long long h45 = hp_[2], h67 = hp_[3];                          \
        float4 wv = *(const float4*)(wt_ + j * G4_ + u4);                       \
        unsigned long long w_;                                                  \
        w_ = pack2(wv.x, wv.x); fma2(acc[0][0], h01, w_); fma2(acc[1][0], h23, w_); fma2(acc[2][0], h45, w_); fma2(acc[3][0], h67, w_); \
        w_ = pack2(wv.y, wv.y); fma2(acc[0][1], h01, w_); fma2(acc[1][1], h23, w_); fma2(acc[2][1], h45, w_); fma2(acc[3][1], h67, w_); \
        w_ = pack2(wv.z, wv.z); fma2(acc[0][2], h01, w_); fma2(acc[1][2], h23, w_); fma2(acc[2][2], h45, w_); fma2(acc[3][2], h67, w_); \
        w_ = pack2(wv.w, wv.w); fma2(acc[0][3], h01, w_); fma2(acc[1][3], h23, w_); fma2(acc[2][3], h45, w_); fma2(acc[3][3], h67, w_); \
    } }

#define ELEMWISE(CS, HS) {                                                      \
    float cb_[8], hb_[8];                                                       \
    *(float4*)&cb_[0] = *(const float4*)&(CS)[srow];                            \
    *(float4*)&cb_[4] = *(const float4*)&(CS)[srow + 4];                        \
    _Pragma("unroll")                                                           \
    for (int p_ = 0; p_ < 4; ++p_) {                                            \
        float2 gi_ = unpack2(acc[p_][0]);                                       \
        float2 gf_ = unpack2(acc[p_][1]);                                       \
        float2 gg_ = unpack2(acc[p_][2]);                                       \
        float2 go_ = unpack2(acc[p_][3]);                                       \
        float c0v_ = sigf(gf_.x) * cb_[2 * p_]     + sigf(gi_.x) * tanhx(gg_.x);\
        float c1v_ = sigf(gf_.y) * cb_[2 * p_ + 1] + sigf(gi_.y) * tanhx(gg_.y);\
        cb_[2 * p_] = c0v_; cb_[2 * p_ + 1] = c1v_;                             \
        hb_[2 * p_]     = sigf(go_.x) * tanhx(c0v_);                            \
        hb_[2 * p_ + 1] = sigf(go_.y) * tanhx(c1v_);                            \
    }                                                                           \
    *(float4*)&(CS)[srow]     = *(float4*)&cb_[0];                              \
    *(float4*)&(CS)[srow + 4] = *(float4*)&cb_[4];                              \
    *(float4*)&(HS)[srow]     = *(float4*)&hb_[0];                              \
    *(float4*)&(HS)[srow + 4] = *(float4*)&hb_[4];                              \
}

// ---------------- main persistent-per-batch-tile kernel ----------------
__global__ void __launch_bounds__(NTHREADS, 1)
lstm_kernel(const float* __restrict__ x,
            const float* __restrict__ headW, const float* __restrict__ headb,
            const float* __restrict__ confW, const float* __restrict__ confb,
            float* __restrict__ out)
{
    extern __shared__ float sm[];
    float* h0s = sm;                   // [H_][ST]
    float* h1s = h0s + H_ * ST;
    float* c0s = h1s + H_ * ST;
    float* c1s = c0s + H_ * ST;
    float* xs  = c1s + H_ * ST;        // [IN_][ST]
    float* prs = xs + IN_ * ST;        // [2][ST]
    float* cfs = prs + 2 * ST;         // [K_][ROWS]

    const int tid = threadIdx.x;
    const int hu  = tid & (H_ - 1);    // hidden unit 0..255
    const int rg  = tid >> 8;          // row group 0..3
    const int r0  = rg * 8;
    const int u4  = hu << 2;
    const int b0  = blockIdx.x * ROWS;
    const int srow = hu * ST + r0;

    for (int i = tid; i < 4 * H_ * ST; i += NTHREADS) sm[i] = 0.f;
    __syncthreads();

    unsigned long long acc[4][4];

    // ================= ENCODER =================
    for (int t = 0; t < T_; ++t) {
        if (tid < IN_ * ROWS) {
            int j = tid & 3, r = tid >> 2;
            xs[j * ST + r] = x[((size_t)(b0 + r) * T_ + t) * IN_ + j];
        }
        __syncthreads();
        // cell 0
        ACC_INIT(g_B0);
        GATE_SEG(xs, IN_, g_WT_ih0);
        GATE_SEG(h0s, H_, g_WT_hh0);
        __syncthreads();
        ELEMWISE(c0s, h0s);
        __syncthreads();
        // cell 1 (input = new h0, recur = h1)
        ACC_INIT(g_B1);
        GATE_SEG(h0s, H_, g_WT_cat1);
        GATE_SEG(h1s, H_, g_WT_cat1 + H_ * G4_);
        __syncthreads();
        ELEMWISE(c1s, h1s);
        __syncthreads();
    }

    // checkpoint encoder state (same-thread RAW later; no extra sync needed)
    {
        int go = hu * B_ + b0 + r0;
        *(float4*)&g_h0e[go]     = *(const float4*)&h0s[srow];
        *(float4*)&g_h0e[go + 4] = *(const float4*)&h0s[srow + 4];
        *(float4*)&g_h1e[go]     = *(const float4*)&h1s[srow];
        *(float4*)&g_h1e[go + 4] = *(const float4*)&h1s[srow + 4];
        *(float4*)&g_c0e[go]     = *(const float4*)&c0s[srow];
        *(float4*)&g_c0e[go + 4] = *(const float4*)&c0s[srow + 4];
        *(float4*)&g_c1e[go]     = *(const float4*)&c1s[srow];
        *(float4*)&g_c1e[go + 4] = *(const float4*)&c1s[srow + 4];
    }

    // confidence head (uses final encoder h1)
    if (tid < K_ * ROWS) {
        int k = tid >> 5, r = tid & 31;
        const float* cw = confW + k * H_;
        float s = confb[k];
#pragma unroll 4
        for (int j = 0; j < H_; ++j) s += h1s[j * ST + r] * cw[j];
        cfs[k * ROWS + r] = s;
    }
    __syncthreads();
    if (tid < ROWS) {
        float l0 = cfs[tid], l1 = cfs[ROWS + tid], l2 = cfs[2 * ROWS + tid];
        float m = fmaxf(l0, fmaxf(l1, l2));
        float e0 = __expf(l0 - m), e1 = __expf(l1 - m), e2 = __expf(l2 - m);
        float inv = 1.f / (e0 + e1 + e2);
        float* co = out + (size_t)B_ * K_ * FS_ * 2 + (size_t)(b0 + tid) * K_;
        co[0] = e0 * inv; co[1] = e1 * inv; co[2] = e2 * inv;
    }

    // ================= DECODER (K modes) =================
    for (int k = 0; k < K_; ++k) {
        __syncthreads();
        {   // restore encoder state
            int go = hu * B_ + b0 + r0;
            *(float4*)&h0s[srow]     = *(const float4*)&g_h0e[go];
            *(float4*)&h0s[srow + 4] = *(const float4*)&g_h0e[go + 4];
            *(float4*)&h1s[srow]     = *(const float4*)&g_h1e[go];
            *(float4*)&h1s[srow + 4] = *(const float4*)&g_h1e[go + 4];
            *(float4*)&c0s[srow]     = *(const float4*)&g_c0e[go];
            *(float4*)&c0s[srow + 4] = *(const float4*)&g_c0e[go + 4];
            *(float4*)&c1s[srow]     = *(const float4*)&g_c1e[go];
            *(float4*)&c1s[srow + 4] = *(const float4*)&g_c1e[go + 4];
        }
        if (tid < 2 * ROWS) {   // dec_input = x[:, -1, :2]
            int o = tid & 1, r = tid >> 1;
            prs[o * ST + r] = x[((size_t)(b0 + r) * T_ + (T_ - 1)) * IN_ + o];
        }
        __syncthreads();

        const float* WDi = g_dWT_ih0[k];
        const float* WD0 = g_dWT_hh0[k];
        const float* WD1 = g_dWT_cat1[k];

        for (int s5 = 0; s5 < FS_; ++s5) {
            ACC_INIT(g_dB0[k]);
            GATE_SEG(prs, 2, WDi);
            GATE_SEG(h0s, H_, WD0);
            __syncthreads();
            ELEMWISE(c0s, h0s);
            __syncthreads();
            ACC_INIT(g_dB1[k]);
            GATE_SEG(h0s, H_, WD1);
            GATE_SEG(h1s, H_, WD1 + H_ * G4_);
            __syncthreads();
            ELEMWISE(c1s, h1s);
            __syncthreads();
            // head -> pred (feedback) + modes output
            if (tid < 2 * ROWS) {
                int o = tid & 1, r = tid >> 1;
                const float* hw = headW + (k * 2 + o) * H_;
                float p = headb[k * 2 + o];
#pragma unroll 4
                for (int j = 0; j < H_; ++j) p += h1s[j * ST + r] * hw[j];
                prs[o * ST + r] = p;
                out[(((size_t)(b0 + r) * K_ + k) * FS_ + s5) * 2 + o] = p;
            }
            __syncthreads();
        }
    }
}

// ---------------- launch ----------------
static const int SMEM_BYTES = (4 * H_ * ST + IN_ * ST + 2 * ST + K_ * ROWS) * (int)sizeof(float);

extern "C" void kernel_launch(void* const* d_in, const int* in_sizes, int n_in,
                              void* d_out, int out_size) {
    const float* x      = (const float*)d_in[0];
    const float* eWih0  = (const float*)d_in[1];
    const float* eWhh0  = (const float*)d_in[2];
    const float* ebih0  = (const float*)d_in[3];
    const float* ebhh0  = (const float*)d_in[4];
    const float* eWih1  = (const float*)d_in[5];
    const float* eWhh1  = (const float*)d_in[6];
    const float* ebih1  = (const float*)d_in[7];
    const float* ebhh1  = (const float*)d_in[8];
    const float* dWih0  = (const float*)d_in[9];
    const float* dWhh0  = (const float*)d_in[10];
    const float* dbih0  = (const float*)d_in[11];
    const float* dbhh0  = (const float*)d_in[12];
    const float* dWih1  = (const float*)d_in[13];
    const float* dWhh1  = (const float*)d_in[14];
    const float* dbih1  = (const float*)d_in[15];
    const float* dbhh1  = (const float*)d_in[16];
    const float* headW  = (const float*)d_in[17];
    const float* headb  = (const float*)d_in[18];
    const float* confW  = (const float*)d_in[19];
    const float* confb  = (const float*)d_in[20];

    cudaFuncSetAttribute(lstm_kernel,
                         cudaFuncAttributeMaxDynamicSharedMemorySize, SMEM_BYTES);

    prep_kernel<<<2048, 512>>>(eWih0, eWhh0, ebih0, ebhh0,
                               eWih1, eWhh1, ebih1, ebhh1,
                               dWih0, dWhh0, dbih0, dbhh0,
                               dWih1, dWhh1, dbih1, dbhh1);
    lstm_kernel<<<NCTA, NTHREADS, SMEM_BYTES>>>(x, headW, headb, confW, confb,
                                                (float*)d_out);
}